// round 10
// baseline (speedup 1.0000x reference)
#include <cuda_runtime.h>
#include <cstdint>

#define KTAGS 16
#define TLEN  512
#define BROWS 1024
#define START_ID 14
#define STOP_ID  15

__device__ float g_row_out[BROWS];
__device__ int   g_ctr = 0;      // last-block counter, self-resetting

typedef unsigned long long u64;

// ---- f32x2 packed helpers ----
__device__ __forceinline__ u64 pk2(float lo, float hi) {
    u64 r; asm("mov.b64 %0, {%1, %2};" : "=l"(r) : "f"(lo), "f"(hi)); return r;
}
__device__ __forceinline__ u64 mul2(u64 a, u64 b) {
    u64 r; asm("mul.rn.f32x2 %0, %1, %2;" : "=l"(r) : "l"(a), "l"(b)); return r;
}
__device__ __forceinline__ u64 fma2(u64 a, u64 b, u64 c) {
    u64 r; asm("fma.rn.f32x2 %0, %1, %2, %3;" : "=l"(r) : "l"(a), "l"(b), "l"(c)); return r;
}
__device__ __forceinline__ u64 add2(u64 a, u64 b) {
    u64 r; asm("add.rn.f32x2 %0, %1, %2;" : "=l"(r) : "l"(a), "l"(b)); return r;
}
__device__ __forceinline__ float hadd2(u64 a) {
    float lo, hi;
    asm("mov.b64 {%0, %1}, %2;" : "=f"(lo), "=f"(hi) : "l"(a));
    return lo + hi;
}
__device__ __forceinline__ unsigned umax2(u64 a) {
    return max((unsigned)a, (unsigned)(a >> 32));
}

// ---------------------------------------------------------------------------
// Fused kernel. 128 threads = 8 groups of 16 lanes; TWO rows per group
// (interleaved independent recursions to hide chain latency at ~1 warp/SMSP).
// Forward recursion in linear domain: alpha_j = C + ln(p_j).
// Exchange via double-buffered smem + one __syncwarp per combined step
// (R6-validated). Exponent-only renorm every 8 steps from stale q registers.
// ---------------------------------------------------------------------------
__global__ void __launch_bounds__(128)
crf_fused_kernel(const float* __restrict__ h,
                 const int*   __restrict__ y32,      // raw y words (int32 view)
                 const float* __restrict__ mask,
                 const float* __restrict__ trans,
                 float* __restrict__ out) {
    __shared__ float tr_s[256];
    __shared__ __align__(16) float pbuf[2][8][2][16]; // [parity][group][rowslot][state]
    __shared__ int   s_ysh;
    __shared__ int   s_last;
    __shared__ float s_red[4];

    const int tid = threadIdx.x;

    if (tid < 64) ((float4*)tr_s)[tid] = ((const float4*)trans)[tid];

    // y dtype detection: int64 layout -> hi 32-bit word of each u64 is 0.
    if (tid < 32) {
        u64 v = ((const u64*)y32)[(size_t)tid * 256];
        unsigned bal = __ballot_sync(0xFFFFFFFFu, (unsigned)(v >> 32) != 0u);
        if (tid == 0) s_ysh = (bal == 0u) ? 1 : 0;
    }
    __syncthreads();

    const int lane = tid & 15;
    const int gid  = tid >> 4;                  // 0..7 group in block
    const unsigned gmask = 0xFFFFu << ((gid & 1) * 16);

    const int row0 = blockIdx.x * 16 + gid * 2; // two consecutive rows per group
    const int ysh = s_ysh;

    const float* hrowA = h + (size_t)row0 * TLEN * KTAGS;
    const float* hrowB = hrowA + (size_t)TLEN * KTAGS;
    const float* mrowA = mask + (size_t)row0 * TLEN;
    const float* mrowB = mrowA + TLEN;
    const int* yrowA = y32 + (((size_t)row0 * TLEN) << ysh);
    const int* yrowB = y32 + (((size_t)(row0 + 1) * TLEN) << ysh);

    // Etr row of this lane, packed: Etr[i] = exp(trans[lane, i]).
    u64 EtrP[8];
#pragma unroll
    for (int k = 0; k < 8; k++)
        EtrP[k] = pk2(__expf(tr_s[lane * 16 + 2 * k]),
                      __expf(tr_s[lane * 16 + 2 * k + 1]));
    const float EtrStop = __expf(tr_s[STOP_ID * 16 + lane]);

    // ---- length + gold score for both rows (interleaved, high MLP) ----
    float lsA = 0.f, gsA = 0.f, lsB = 0.f, gsB = 0.f;
#pragma unroll 2
    for (int k = lane; k < TLEN; k += 16) {
        float ma = mrowA[k], mb = mrowB[k];
        int yta = yrowA[k << ysh], ytb = yrowB[k << ysh];
        int ypa = (k == 0) ? START_ID : yrowA[(k - 1) << ysh];
        int ypb = (k == 0) ? START_ID : yrowB[(k - 1) << ysh];
        lsA += ma;  lsB += mb;
        gsA = fmaf(ma, hrowA[k * 16 + yta] + tr_s[yta * 16 + ypa], gsA);
        gsB = fmaf(mb, hrowB[k * 16 + ytb] + tr_s[ytb * 16 + ypb], gsB);
    }
#pragma unroll
    for (int s = 8; s; s >>= 1) {
        lsA += __shfl_xor_sync(gmask, lsA, s, 16);
        gsA += __shfl_xor_sync(gmask, gsA, s, 16);
        lsB += __shfl_xor_sync(gmask, lsB, s, 16);
        gsB += __shfl_xor_sync(gmask, gsB, s, 16);
    }
    const int lenA = (int)(lsA + 0.5f);
    const int lenB = (int)(lsB + 0.5f);
    const float goldA = gsA + tr_s[STOP_ID * 16 + yrowA[(lenA - 1) << ysh]];
    const float goldB = gsB + tr_s[STOP_ID * 16 + yrowB[(lenB - 1) << ysh]];

    // warp-uniform trip count
    int steps = (max(lenA, lenB) + 7) & ~7;
    steps = max(steps, __shfl_xor_sync(0xFFFFFFFFu, steps, 16));

    // ---- forward recursions (two independent chains) ----
    float pA = (lane == START_ID) ? 1.0f : 0.0f;
    float pB = pA;
    float CA = 0.0f, CB = 0.0f;

    float hbA[8], hbB[8];
#pragma unroll
    for (int d = 0; d < 8; d++) { hbA[d] = hrowA[d * 16 + lane];
                                  hbB[d] = hrowB[d * 16 + lane]; }

    for (int t0 = 0; t0 < steps; t0 += 8) {
        float ehA[8], ehB[8];
#pragma unroll
        for (int u = 0; u < 8; u++) { ehA[u] = __expf(hbA[u]);
                                      ehB[u] = __expf(hbB[u]); }
#pragma unroll
        for (int u = 0; u < 8; u++) {
            int idx = min(t0 + u + 8, TLEN - 1) * 16 + lane;
            hbA[u] = hrowA[idx];
            hbB[u] = hrowB[idx];
        }

        unsigned muA = 0u, muB = 0u;   // stale-by-1 lane-local max (u==7)

#pragma unroll
        for (int u = 0; u < 8; u++) {
            const bool actA = (t0 + u) < lenA;
            const bool actB = (t0 + u) < lenB;
            float* bufA = pbuf[u & 1][gid][0];
            float* bufB = pbuf[u & 1][gid][1];
            bufA[lane] = pA;
            bufB[lane] = pB;
            __syncwarp();
            const ulonglong2* ap = (const ulonglong2*)bufA;
            const ulonglong2* bp = (const ulonglong2*)bufB;
            const ulonglong2 a0v = ap[0], a1v = ap[1], a2v = ap[2], a3v = ap[3];
            const ulonglong2 b0v = bp[0], b1v = bp[1], b2v = bp[2], b3v = bp[3];

            u64 ra0 = fma2(a0v.y, EtrP[1], mul2(a0v.x, EtrP[0]));
            u64 rb0 = fma2(b0v.y, EtrP[1], mul2(b0v.x, EtrP[0]));
            u64 ra1 = fma2(a1v.y, EtrP[3], mul2(a1v.x, EtrP[2]));
            u64 rb1 = fma2(b1v.y, EtrP[3], mul2(b1v.x, EtrP[2]));
            u64 ra2 = fma2(a2v.y, EtrP[5], mul2(a2v.x, EtrP[4]));
            u64 rb2 = fma2(b2v.y, EtrP[5], mul2(b2v.x, EtrP[4]));
            u64 ra3 = fma2(a3v.y, EtrP[7], mul2(a3v.x, EtrP[6]));
            u64 rb3 = fma2(b3v.y, EtrP[7], mul2(b3v.x, EtrP[6]));
            float SA = hadd2(add2(add2(ra0, ra1), add2(ra2, ra3)));
            float SB = hadd2(add2(add2(rb0, rb1), add2(rb2, rb3)));
            float pnA = SA * ehA[u];
            float pnB = SB * ehB[u];
            pA = actA ? pnA : pA;
            pB = actB ? pnB : pB;

            if (u == 7) {
                muA = max(max(max(umax2(a0v.x), umax2(a0v.y)),
                              max(umax2(a1v.x), umax2(a1v.y))),
                          max(max(umax2(a2v.x), umax2(a2v.y)),
                              max(umax2(a3v.x), umax2(a3v.y))));
                muB = max(max(max(umax2(b0v.x), umax2(b0v.y)),
                              max(umax2(b1v.x), umax2(b1v.y))),
                          max(max(umax2(b2v.x), umax2(b2v.y)),
                              max(umax2(b3v.x), umax2(b3v.y))));
            }
        }
        // exponent-only renorm: exact power-of-2 scaling, no-op for frozen rows
        int meA = max((int)(muA >> 23), 1);
        int meB = max((int)(muB >> 23), 1);
        float scA = __uint_as_float((unsigned)(254 - meA) << 23);
        float scB = __uint_as_float((unsigned)(254 - meB) << 23);
        CA += (float)(meA - 127) * 0.6931471805599453f;
        CB += (float)(meB - 127) * 0.6931471805599453f;
        pA *= scA;
        pB *= scB;
    }

    // fwd = C + ln( sum_j p_j * exp(trans[STOP, j]) )
    float vA = pA * EtrStop;
    float vB = pB * EtrStop;
#pragma unroll
    for (int s = 8; s; s >>= 1) {
        vA += __shfl_xor_sync(gmask, vA, s, 16);
        vB += __shfl_xor_sync(gmask, vB, s, 16);
    }
    if (lane == 0) {
        g_row_out[row0]     = CA + __logf(vA) - goldA;
        g_row_out[row0 + 1] = CB + __logf(vB) - goldB;
    }

    // ---- last-block mean reduction ----
    __threadfence();
    __syncthreads();
    if (tid == 0) {
        int old = atomicAdd(&g_ctr, 1);
        s_last = (old == gridDim.x - 1);
    }
    __syncthreads();
    if (s_last) {
        float s = 0.f;
#pragma unroll
        for (int i = 0; i < BROWS / 128; i++)
            s += g_row_out[tid + i * 128];
#pragma unroll
        for (int sft = 16; sft; sft >>= 1)
            s += __shfl_xor_sync(0xFFFFFFFFu, s, sft);
        if ((tid & 31) == 0) s_red[tid >> 5] = s;
        __syncthreads();
        if (tid == 0) {
            float tot = s_red[0] + s_red[1] + s_red[2] + s_red[3];
            out[0] = tot * (1.0f / (float)BROWS);
            g_ctr = 0;   // reset for next graph replay
        }
    }
}

// ---------------------------------------------------------------------------
extern "C" void kernel_launch(void* const* d_in, const int* in_sizes, int n_in,
                              void* d_out, int out_size) {
    const float* h     = (const float*)d_in[0];
    const int*   y     = (const int*)d_in[1];
    const float* mask  = (const float*)d_in[2];
    const float* trans = (const float*)d_in[3];
    float* out = (float*)d_out;

    crf_fused_kernel<<<BROWS / 16, 128>>>(h, y, mask, trans, out);
}

// round 11
// speedup vs baseline: 1.2895x; 1.2895x over previous
#include <cuda_runtime.h>
#include <cstdint>

#define KTAGS 16
#define TLEN  512
#define BROWS 1024
#define START_ID 14
#define STOP_ID  15

__device__ float g_row_out[BROWS];
__device__ int   g_ctr = 0;      // last-block counter, self-resetting

typedef unsigned long long u64;

// ---- f32x2 packed helpers ----
__device__ __forceinline__ u64 pk2(float lo, float hi) {
    u64 r; asm("mov.b64 %0, {%1, %2};" : "=l"(r) : "f"(lo), "f"(hi)); return r;
}
__device__ __forceinline__ u64 mul2(u64 a, u64 b) {
    u64 r; asm("mul.rn.f32x2 %0, %1, %2;" : "=l"(r) : "l"(a), "l"(b)); return r;
}
__device__ __forceinline__ u64 fma2(u64 a, u64 b, u64 c) {
    u64 r; asm("fma.rn.f32x2 %0, %1, %2, %3;" : "=l"(r) : "l"(a), "l"(b), "l"(c)); return r;
}
__device__ __forceinline__ u64 add2(u64 a, u64 b) {
    u64 r; asm("add.rn.f32x2 %0, %1, %2;" : "=l"(r) : "l"(a), "l"(b)); return r;
}
__device__ __forceinline__ float hadd2(u64 a) {
    float lo, hi;
    asm("mov.b64 {%0, %1}, %2;" : "=f"(lo), "=f"(hi) : "l"(a));
    return lo + hi;
}

// ---------------------------------------------------------------------------
// Fused kernel. 128 threads = 8 groups of 16 lanes; one group per batch row.
// Forward recursion in linear domain: alpha_j = C + ln(p_j).
// R6-validated exchange: double-buffered smem, STS + __syncwarp + 4x LDS.128.
// The recursion runs UNCONDITIONALLY (no select on the loop-carried chain);
// the row's answer is snapshotted off-chain at t == len-1 (pfin, Cfin).
// Exponent-only renorm every 8 steps from stale q registers (exact).
// ---------------------------------------------------------------------------
__global__ void __launch_bounds__(128)
crf_fused_kernel(const float* __restrict__ h,
                 const int*   __restrict__ y32,      // raw y words (int32 view)
                 const float* __restrict__ mask,
                 const float* __restrict__ trans,
                 float* __restrict__ out) {
    __shared__ float tr_s[256];
    __shared__ __align__(16) float pbuf[2][8][16];   // [parity][group][state]
    __shared__ int   s_ysh;
    __shared__ int   s_last;
    __shared__ float s_red[4];

    const int tid = threadIdx.x;

    if (tid < 64) ((float4*)tr_s)[tid] = ((const float4*)trans)[tid];

    // y dtype detection: int64 layout -> hi 32-bit word of each u64 is 0.
    if (tid < 32) {
        u64 v = ((const u64*)y32)[(size_t)tid * 256];
        unsigned bal = __ballot_sync(0xFFFFFFFFu, (unsigned)(v >> 32) != 0u);
        if (tid == 0) s_ysh = (bal == 0u) ? 1 : 0;
    }
    __syncthreads();

    const int lane = tid & 15;
    const int gid  = tid >> 4;                  // 0..7 group in block
    const int row  = blockIdx.x * 8 + gid;
    const unsigned gmask = 0xFFFFu << ((gid & 1) * 16);

    const float* hrow = h    + (size_t)row * TLEN * KTAGS;
    const float* mrow = mask + (size_t)row * TLEN;
    const int ysh = s_ysh;
    const int* yrow = y32 + (((size_t)row * TLEN) << ysh);

    // Etr row of this lane, packed: Etr[i] = exp(trans[lane, i]).
    u64 EtrP[8];
#pragma unroll
    for (int k = 0; k < 8; k++)
        EtrP[k] = pk2(__expf(tr_s[lane * 16 + 2 * k]),
                      __expf(tr_s[lane * 16 + 2 * k + 1]));
    const float EtrStop = __expf(tr_s[STOP_ID * 16 + lane]);

    // ---- length + gold score (branchless, lane-parallel) ----
    float lsum = 0.f, gsum = 0.f;
#pragma unroll 4
    for (int k = lane; k < TLEN; k += 16) {
        float mk = mrow[k];
        int yt = yrow[k << ysh];
        int yp = (k == 0) ? START_ID : yrow[(k - 1) << ysh];
        lsum += mk;
        gsum = fmaf(mk, hrow[k * 16 + yt] + tr_s[yt * 16 + yp], gsum);
    }
#pragma unroll
    for (int s = 8; s; s >>= 1) {
        lsum += __shfl_xor_sync(gmask, lsum, s, 16);
        gsum += __shfl_xor_sync(gmask, gsum, s, 16);
    }
    const int len = (int)(lsum + 0.5f);
    const int lastTag = yrow[(len - 1) << ysh];
    const float gold = gsum + tr_s[STOP_ID * 16 + lastTag];
    const int lenm1 = len - 1;

    // warp-uniform trip count: max over both groups, rounded up to 8
    int steps = (len + 7) & ~7;
    steps = max(steps, __shfl_xor_sync(0xFFFFFFFFu, steps, 16));

    // ---- forward recursion (unconditional; snapshot at t == len-1) ----
    float p = (lane == START_ID) ? 1.0f : 0.0f;
    float C = 0.0f;
    float pfin = 0.0f, Cfin = 0.0f;

    float hb[8];
#pragma unroll
    for (int d = 0; d < 8; d++) hb[d] = hrow[d * 16 + lane];

    for (int t0 = 0; t0 < steps; t0 += 8) {
        float eh[8];
#pragma unroll
        for (int u = 0; u < 8; u++) eh[u] = __expf(hb[u]);
#pragma unroll
        for (int u = 0; u < 8; u++)
            hb[u] = hrow[min(t0 + u + 8, TLEN - 1) * 16 + lane];

        unsigned mu = 0u;       // stale-by-1 lane-local max of q bits (u==7)

#pragma unroll
        for (int u = 0; u < 8; u++) {
            float* buf = pbuf[u & 1][gid];
            buf[lane] = p;
            __syncwarp();
            const ulonglong2* bp = (const ulonglong2*)buf;
            const ulonglong2 v0 = bp[0];
            const ulonglong2 v1 = bp[1];
            const ulonglong2 v2 = bp[2];
            const ulonglong2 v3 = bp[3];

            u64 a0 = fma2(v0.y, EtrP[1], mul2(v0.x, EtrP[0]));
            u64 a1 = fma2(v1.y, EtrP[3], mul2(v1.x, EtrP[2]));
            u64 a2 = fma2(v2.y, EtrP[5], mul2(v2.x, EtrP[4]));
            u64 a3 = fma2(v3.y, EtrP[7], mul2(v3.x, EtrP[6]));
            float S = hadd2(add2(add2(a0, a1), add2(a2, a3)));
            p = S * eh[u];                   // loop-carried: no select

            // off-chain snapshot of the row's final state
            pfin = ((t0 + u) == lenm1) ? p : pfin;

            if (u == 7) {
                unsigned m0 = max((unsigned)v0.x, (unsigned)(v0.x >> 32));
                unsigned m1 = max((unsigned)v0.y, (unsigned)(v0.y >> 32));
                unsigned m2 = max((unsigned)v1.x, (unsigned)(v1.x >> 32));
                unsigned m3 = max((unsigned)v1.y, (unsigned)(v1.y >> 32));
                unsigned m4 = max((unsigned)v2.x, (unsigned)(v2.x >> 32));
                unsigned m5 = max((unsigned)v2.y, (unsigned)(v2.y >> 32));
                unsigned m6 = max((unsigned)v3.x, (unsigned)(v3.x >> 32));
                unsigned m7 = max((unsigned)v3.y, (unsigned)(v3.y >> 32));
                mu = max(max(max(m0, m1), max(m2, m3)),
                         max(max(m4, m5), max(m6, m7)));
            }
        }
        // capture C for the block containing the snapshot (pfin was taken
        // before this block's renorm update, so Cfin = C at block entry)
        Cfin = ((unsigned)(lenm1 - t0) < 8u) ? C : Cfin;

        // exponent-only renorm: exact for any power-of-2 scale
        int me = (int)(mu >> 23);
        me = (me < 1) ? 1 : me;
        float scale = __uint_as_float((unsigned)(254 - me) << 23);  // 2^(127-me)
        C += (float)(me - 127) * 0.6931471805599453f;
        p *= scale;
    }

    // fwd = Cfin + ln( sum_j pfin_j * exp(trans[STOP, j]) )
    float v = pfin * EtrStop;
#pragma unroll
    for (int s = 8; s; s >>= 1)
        v += __shfl_xor_sync(gmask, v, s, 16);
    const float fwd = Cfin + __logf(v);

    if (lane == 0) g_row_out[row] = fwd - gold;

    // ---- last-block mean reduction ----
    __threadfence();
    __syncthreads();
    if (tid == 0) {
        int old = atomicAdd(&g_ctr, 1);
        s_last = (old == gridDim.x - 1);
    }
    __syncthreads();
    if (s_last) {
        float s = 0.f;
#pragma unroll
        for (int i = 0; i < BROWS / 128; i++)
            s += g_row_out[tid + i * 128];
#pragma unroll
        for (int sft = 16; sft; sft >>= 1)
            s += __shfl_xor_sync(0xFFFFFFFFu, s, sft);
        if ((tid & 31) == 0) s_red[tid >> 5] = s;
        __syncthreads();
        if (tid == 0) {
            float tot = s_red[0] + s_red[1] + s_red[2] + s_red[3];
            out[0] = tot * (1.0f / (float)BROWS);
            g_ctr = 0;   // reset for next graph replay
        }
    }
}

// ---------------------------------------------------------------------------
extern "C" void kernel_launch(void* const* d_in, const int* in_sizes, int n_in,
                              void* d_out, int out_size) {
    const float* h     = (const float*)d_in[0];
    const int*   y     = (const int*)d_in[1];
    const float* mask  = (const float*)d_in[2];
    const float* trans = (const float*)d_in[3];
    float* out = (float*)d_out;

    crf_fused_kernel<<<BROWS / 8, 128>>>(h, y, mask, trans, out);
}

// round 12
// speedup vs baseline: 1.9076x; 1.4793x over previous
#include <cuda_runtime.h>
#include <cstdint>

#define KTAGS 16
#define TLEN  512
#define BROWS 1024
#define START_ID 14
#define STOP_ID  15

__device__ float g_row_out[BROWS];
__device__ int   g_ctr = 0;      // last-block counter, self-resetting

typedef unsigned long long u64;

// ---- f32x2 packed helpers ----
__device__ __forceinline__ u64 pk2(float lo, float hi) {
    u64 r; asm("mov.b64 %0, {%1, %2};" : "=l"(r) : "f"(lo), "f"(hi)); return r;
}
__device__ __forceinline__ u64 mul2(u64 a, u64 b) {
    u64 r; asm("mul.rn.f32x2 %0, %1, %2;" : "=l"(r) : "l"(a), "l"(b)); return r;
}
__device__ __forceinline__ u64 fma2(u64 a, u64 b, u64 c) {
    u64 r; asm("fma.rn.f32x2 %0, %1, %2, %3;" : "=l"(r) : "l"(a), "l"(b), "l"(c)); return r;
}
__device__ __forceinline__ u64 add2(u64 a, u64 b) {
    u64 r; asm("add.rn.f32x2 %0, %1, %2;" : "=l"(r) : "l"(a), "l"(b)); return r;
}
__device__ __forceinline__ float hadd2(u64 a) {
    float lo, hi;
    asm("mov.b64 {%0, %1}, %2;" : "=f"(lo), "=f"(hi) : "l"(a));
    return lo + hi;
}

// ---------------------------------------------------------------------------
// Meet-in-the-middle CRF. One 32-lane warp per batch row:
//   lanes 0-15  : forward chain  p <- eh_t (.) (Etr  p),  t = 0 .. m-1
//   lanes 16-31 : adjoint chain  w <- eh_t (.) (EtrT w),  t = len-2 .. m
// Both chains share ONE instruction stream (R6 body); only per-lane constants
// differ. Stitch: score = C_f + C_b + ln( sum_j w_m[j] * (Etr p_m)[j] ).
// Exchange: double-buffered smem, STS + __syncwarp + 4x LDS.128 (R6-validated).
// Exponent-only renorm every 8 steps from stale exchanged values (exact).
// ---------------------------------------------------------------------------
__global__ void __launch_bounds__(128)
crf_fused_kernel(const float* __restrict__ h,
                 const int*   __restrict__ y32,      // raw y words (int32 view)
                 const float* __restrict__ mask,
                 const float* __restrict__ trans,
                 float* __restrict__ out) {
    __shared__ float tr_s[256];
    __shared__ __align__(16) float pbuf[2][4][2][16]; // [parity][warp][grp][state]
    __shared__ int   s_ysh;
    __shared__ int   s_last;
    __shared__ float s_red[4];

    const int tid = threadIdx.x;

    if (tid < 64) ((float4*)tr_s)[tid] = ((const float4*)trans)[tid];

    // y dtype detection: int64 layout -> hi 32-bit word of each u64 is 0.
    if (tid < 32) {
        u64 v = ((const u64*)y32)[(size_t)tid * 256];
        unsigned bal = __ballot_sync(0xFFFFFFFFu, (unsigned)(v >> 32) != 0u);
        if (tid == 0) s_ysh = (bal == 0u) ? 1 : 0;
    }
    __syncthreads();

    const int wid   = tid >> 5;          // warp in block (0..3)
    const int lane  = tid & 31;
    const int grp   = lane >> 4;         // 0 = forward, 1 = backward
    const int j     = lane & 15;         // state index
    const int row   = blockIdx.x * 4 + wid;

    const float* hrow = h    + (size_t)row * TLEN * KTAGS;
    const float* mrow = mask + (size_t)row * TLEN;
    const int ysh = s_ysh;
    const int* yrow = y32 + (((size_t)row * TLEN) << ysh);

    // M row for this lane: fwd -> Etr[j,i] = exp(trans[j,i]);
    //                      bwd -> EtrT[j,i] = exp(trans[i,j]).
    u64 EtrP[8];
#pragma unroll
    for (int k = 0; k < 8; k++) {
        int i0 = 2 * k, i1 = 2 * k + 1;
        float e0 = __expf(grp ? tr_s[i0 * 16 + j] : tr_s[j * 16 + i0]);
        float e1 = __expf(grp ? tr_s[i1 * 16 + j] : tr_s[j * 16 + i1]);
        EtrP[k] = pk2(e0, e1);
    }

    // ---- length + gold score (branchless, full 32-lane warp) ----
    float lsum = 0.f, gsum = 0.f;
#pragma unroll 2
    for (int k = lane; k < TLEN; k += 32) {
        float mk = mrow[k];
        int yt = yrow[k << ysh];
        int yp = (k == 0) ? START_ID : yrow[(k - 1) << ysh];
        lsum += mk;
        gsum = fmaf(mk, hrow[k * 16 + yt] + tr_s[yt * 16 + yp], gsum);
    }
#pragma unroll
    for (int s = 16; s; s >>= 1) {
        lsum += __shfl_xor_sync(0xFFFFFFFFu, lsum, s);
        gsum += __shfl_xor_sync(0xFFFFFFFFu, gsum, s);
    }
    const int len = (int)(lsum + 0.5f);
    const int lastTag = yrow[(len - 1) << ysh];
    const float gold = gsum + tr_s[STOP_ID * 16 + lastTag];

    // split: forward does m steps, backward does len-1-m steps
    const int m    = (len - 1) >> 1;
    const int cntF = m;
    const int cntB = len - 1 - m;
    const int cnt  = grp ? cntB : cntF;          // this lane's active steps
    const int trip = (max(cntF, cntB) + 7) & ~7; // warp-uniform

    // ---- init per-lane state ----
    // fwd: p_0 = basis at START.  bwd: w_{len-1} = eh_{len-1} (.) exp(trans[STOP,:])
    float p;
    if (grp == 0) {
        p = (j == START_ID) ? 1.0f : 0.0f;
    } else {
        p = __expf(hrow[(len - 1) * 16 + j]) * __expf(tr_s[STOP_ID * 16 + j]);
    }
    float C = 0.0f;

    // emit index streams: fwd -> s ; bwd -> len-2-s (clamped)
    float hb[8];
#pragma unroll
    for (int d = 0; d < 8; d++) {
        int idx = grp ? max(len - 2 - d, 0) : d;
        hb[d] = hrow[idx * 16 + j];
    }

    for (int s0 = 0; s0 < trip; s0 += 8) {
        float eh[8];
#pragma unroll
        for (int u = 0; u < 8; u++) eh[u] = __expf(hb[u]);
#pragma unroll
        for (int u = 0; u < 8; u++) {
            int sn = s0 + u + 8;
            int idx = grp ? max(len - 2 - sn, 0) : min(sn, TLEN - 1);
            hb[u] = hrow[idx * 16 + j];
        }

        unsigned mu = 0u;       // stale-by-1 lane-local max of exchanged bits

#pragma unroll
        for (int u = 0; u < 8; u++) {
            const bool act = (s0 + u) < cnt;     // per-lane FSEL
            float* buf = pbuf[u & 1][wid][grp];
            buf[j] = p;
            __syncwarp();
            const ulonglong2* bp = (const ulonglong2*)buf;
            const ulonglong2 v0 = bp[0];
            const ulonglong2 v1 = bp[1];
            const ulonglong2 v2 = bp[2];
            const ulonglong2 v3 = bp[3];

            u64 a0 = fma2(v0.y, EtrP[1], mul2(v0.x, EtrP[0]));
            u64 a1 = fma2(v1.y, EtrP[3], mul2(v1.x, EtrP[2]));
            u64 a2 = fma2(v2.y, EtrP[5], mul2(v2.x, EtrP[4]));
            u64 a3 = fma2(v3.y, EtrP[7], mul2(v3.x, EtrP[6]));
            float S = hadd2(add2(add2(a0, a1), add2(a2, a3)));
            float pn = S * eh[u];
            p = act ? pn : p;

            if (u == 7) {
                unsigned m0 = max((unsigned)v0.x, (unsigned)(v0.x >> 32));
                unsigned m1 = max((unsigned)v0.y, (unsigned)(v0.y >> 32));
                unsigned m2 = max((unsigned)v1.x, (unsigned)(v1.x >> 32));
                unsigned m3 = max((unsigned)v1.y, (unsigned)(v1.y >> 32));
                unsigned m4 = max((unsigned)v2.x, (unsigned)(v2.x >> 32));
                unsigned m5 = max((unsigned)v2.y, (unsigned)(v2.y >> 32));
                unsigned m6 = max((unsigned)v3.x, (unsigned)(v3.x >> 32));
                unsigned m7 = max((unsigned)v3.y, (unsigned)(v3.y >> 32));
                mu = max(max(max(m0, m1), max(m2, m3)),
                         max(max(m4, m5), max(m6, m7)));
            }
        }
        // exponent-only renorm: exact power-of-2 scaling (per-group uniform;
        // no-op for frozen chains since exchanged values are then constant)
        int me = (int)(mu >> 23);
        me = (me < 1) ? 1 : me;
        float scale = __uint_as_float((unsigned)(254 - me) << 23);  // 2^(127-me)
        C += (float)(me - 127) * 0.6931471805599453f;
        p *= scale;
    }

    // ---- stitch: score = C_f + C_b + ln( sum_j w_m[j] * (Etr p_m)[j] ) ----
    {
        float* buf = pbuf[0][wid][grp];
        buf[j] = p;
        __syncwarp();
        const ulonglong2* bp = (const ulonglong2*)buf;
        const ulonglong2 v0 = bp[0];
        const ulonglong2 v1 = bp[1];
        const ulonglong2 v2 = bp[2];
        const ulonglong2 v3 = bp[3];
        u64 a0 = fma2(v0.y, EtrP[1], mul2(v0.x, EtrP[0]));
        u64 a1 = fma2(v1.y, EtrP[3], mul2(v1.x, EtrP[2]));
        u64 a2 = fma2(v2.y, EtrP[5], mul2(v2.x, EtrP[4]));
        u64 a3 = fma2(v3.y, EtrP[7], mul2(v3.x, EtrP[6]));
        float S = hadd2(add2(add2(a0, a1), add2(a2, a3)));  // fwd lanes: (Etr p_m)[j]

        float wsw = __shfl_xor_sync(0xFFFFFFFFu, p, 16);    // fwd lane j <- w_m[j]
        float Csw = __shfl_xor_sync(0xFFFFFFFFu, C, 16);    // fwd lane <- C_b

        float v = S * wsw;
#pragma unroll
        for (int s = 8; s; s >>= 1)
            v += __shfl_xor_sync(0xFFFFFFFFu, v, s, 16);

        if (lane == 0) {
            float fwd = C + Csw + __logf(v);
            g_row_out[row] = fwd - gold;
        }
    }

    // ---- last-block mean reduction ----
    __threadfence();
    __syncthreads();
    if (tid == 0) {
        int old = atomicAdd(&g_ctr, 1);
        s_last = (old == gridDim.x - 1);
    }
    __syncthreads();
    if (s_last) {
        float s = 0.f;
#pragma unroll
        for (int i = 0; i < BROWS / 128; i++)
            s += g_row_out[tid + i * 128];
#pragma unroll
        for (int sft = 16; sft; sft >>= 1)
            s += __shfl_xor_sync(0xFFFFFFFFu, s, sft);
        if ((tid & 31) == 0) s_red[tid >> 5] = s;
        __syncthreads();
        if (tid == 0) {
            float tot = s_red[0] + s_red[1] + s_red[2] + s_red[3];
            out[0] = tot * (1.0f / (float)BROWS);
            g_ctr = 0;   // reset for next graph replay
        }
    }
}

// ---------------------------------------------------------------------------
extern "C" void kernel_launch(void* const* d_in, const int* in_sizes, int n_in,
                              void* d_out, int out_size) {
    const float* h     = (const float*)d_in[0];
    const int*   y     = (const int*)d_in[1];
    const float* mask  = (const float*)d_in[2];
    const float* trans = (const float*)d_in[3];
    float* out = (float*)d_out;

    crf_fused_kernel<<<BROWS / 4, 128>>>(h, y, mask, trans, out);
}

// round 13
// speedup vs baseline: 2.0720x; 1.0862x over previous
#include <cuda_runtime.h>
#include <cstdint>

#define KTAGS 16
#define TLEN  512
#define BROWS 1024
#define START_ID 14
#define STOP_ID  15

__device__ float g_row_out[BROWS];
__device__ int   g_ctr = 0;      // last-block counter, self-resetting

typedef unsigned long long u64;

// ---- f32x2 packed helpers ----
__device__ __forceinline__ u64 pk2(float lo, float hi) {
    u64 r; asm("mov.b64 %0, {%1, %2};" : "=l"(r) : "f"(lo), "f"(hi)); return r;
}
__device__ __forceinline__ u64 mul2(u64 a, u64 b) {
    u64 r; asm("mul.rn.f32x2 %0, %1, %2;" : "=l"(r) : "l"(a), "l"(b)); return r;
}
__device__ __forceinline__ u64 fma2(u64 a, u64 b, u64 c) {
    u64 r; asm("fma.rn.f32x2 %0, %1, %2, %3;" : "=l"(r) : "l"(a), "l"(b), "l"(c)); return r;
}
__device__ __forceinline__ u64 add2(u64 a, u64 b) {
    u64 r; asm("add.rn.f32x2 %0, %1, %2;" : "=l"(r) : "l"(a), "l"(b)); return r;
}
__device__ __forceinline__ float hadd2(u64 a) {
    float lo, hi;
    asm("mov.b64 {%0, %1}, %2;" : "=f"(lo), "=f"(hi) : "l"(a));
    return lo + hi;
}

// ---------------------------------------------------------------------------
// Meet-in-the-middle CRF. One 32-lane warp per batch row:
//   lanes 0-15  : forward chain  p <- eh_t (.) (Etr  p),  t = 0 .. m-1
//   lanes 16-31 : adjoint chain  w <- eh_t (.) (EtrT w),  t = len-2 .. m
// Stitch: score = C_f + C_b + ln( sum_j w_m[j] * (Etr p_m)[j] ).
// Prologue restructured for MLP: len from float4 mask loads first, then the
// gold pass in two MLP-8 batches (loads hoisted, dependent gathers batched).
// ---------------------------------------------------------------------------
__global__ void __launch_bounds__(128)
crf_fused_kernel(const float* __restrict__ h,
                 const int*   __restrict__ y32,      // raw y words (int32 view)
                 const float* __restrict__ mask,
                 const float* __restrict__ trans,
                 float* __restrict__ out) {
    __shared__ float tr_s[256];
    __shared__ __align__(16) float pbuf[2][4][2][16]; // [parity][warp][grp][state]
    __shared__ int   s_ysh;
    __shared__ int   s_last;
    __shared__ float s_red[4];

    const int tid = threadIdx.x;

    if (tid < 64) ((float4*)tr_s)[tid] = ((const float4*)trans)[tid];

    // y dtype detection: int64 layout -> hi 32-bit word of each u64 is 0.
    if (tid < 32) {
        u64 v = ((const u64*)y32)[(size_t)tid * 256];
        unsigned bal = __ballot_sync(0xFFFFFFFFu, (unsigned)(v >> 32) != 0u);
        if (tid == 0) s_ysh = (bal == 0u) ? 1 : 0;
    }
    __syncthreads();

    const int wid   = tid >> 5;          // warp in block (0..3)
    const int lane  = tid & 31;
    const int grp   = lane >> 4;         // 0 = forward, 1 = backward
    const int j     = lane & 15;         // state index
    const int row   = blockIdx.x * 4 + wid;

    const float* hrow = h    + (size_t)row * TLEN * KTAGS;
    const float* mrow = mask + (size_t)row * TLEN;
    const int ysh = s_ysh;
    const int* yrow = y32 + (((size_t)row * TLEN) << ysh);

    // ---- fast length: float4 mask loads (full MLP), one warp reduce ----
    float lsum;
    {
        const float4* m4 = (const float4*)mrow;
        float4 a = m4[lane];
        float4 b = m4[lane + 32];
        float4 c = m4[lane + 64];
        float4 d = m4[lane + 96];
        lsum = (a.x + a.y + a.z + a.w) + (b.x + b.y + b.z + b.w)
             + (c.x + c.y + c.z + c.w) + (d.x + d.y + d.z + d.w);
#pragma unroll
        for (int s = 16; s; s >>= 1)
            lsum += __shfl_xor_sync(0xFFFFFFFFu, lsum, s);
    }
    const int len = (int)(lsum + 0.5f);

    // M row for this lane: fwd -> Etr[j,i] = exp(trans[j,i]);
    //                      bwd -> EtrT[j,i] = exp(trans[i,j]).
    u64 EtrP[8];
#pragma unroll
    for (int k = 0; k < 8; k++) {
        int i0 = 2 * k, i1 = 2 * k + 1;
        float e0 = __expf(grp ? tr_s[i0 * 16 + j] : tr_s[j * 16 + i0]);
        float e1 = __expf(grp ? tr_s[i1 * 16 + j] : tr_s[j * 16 + i1]);
        EtrP[k] = pk2(e0, e1);
    }

    // ---- init per-lane chain state (issues its DRAM load early) ----
    float p;
    if (grp == 0) {
        p = (j == START_ID) ? 1.0f : 0.0f;
    } else {
        p = __expf(hrow[(len - 1) * 16 + j]) * __expf(tr_s[STOP_ID * 16 + j]);
    }
    float C = 0.0f;

    // emit prefetch (issues early, overlaps gold pass below)
    float hb[8];
#pragma unroll
    for (int d = 0; d < 8; d++) {
        int idx = grp ? max(len - 2 - d, 0) : d;
        hb[d] = hrow[idx * 16 + j];
    }

    // ---- gold score: two MLP-8 batches ----
    float gsum = 0.f;
#pragma unroll
    for (int half = 0; half < 2; half++) {
        float mk[8];
        int   yt[8], yp[8];
#pragma unroll
        for (int i = 0; i < 8; i++) {
            int k = lane + (half * 8 + i) * 32;
            mk[i] = mrow[k];
            yt[i] = yrow[k << ysh];
            yp[i] = (k == 0) ? START_ID : yrow[(k - 1) << ysh];
        }
        float ev[8];
#pragma unroll
        for (int i = 0; i < 8; i++) {
            int k = lane + (half * 8 + i) * 32;
            ev[i] = hrow[k * 16 + yt[i]];
        }
#pragma unroll
        for (int i = 0; i < 8; i++)
            gsum = fmaf(mk[i], ev[i] + tr_s[yt[i] * 16 + yp[i]], gsum);
    }
#pragma unroll
    for (int s = 16; s; s >>= 1)
        gsum += __shfl_xor_sync(0xFFFFFFFFu, gsum, s);
    const float gold = gsum + tr_s[STOP_ID * 16 + yrow[(len - 1) << ysh]];

    // split: forward does m steps, backward does len-1-m steps
    const int m    = (len - 1) >> 1;
    const int cntF = m;
    const int cntB = len - 1 - m;
    const int cnt  = grp ? cntB : cntF;          // this lane's active steps
    const int trip = (max(cntF, cntB) + 7) & ~7; // warp-uniform

    for (int s0 = 0; s0 < trip; s0 += 8) {
        float eh[8];
#pragma unroll
        for (int u = 0; u < 8; u++) eh[u] = __expf(hb[u]);
#pragma unroll
        for (int u = 0; u < 8; u++) {
            int sn = s0 + u + 8;
            int idx = grp ? max(len - 2 - sn, 0) : min(sn, TLEN - 1);
            hb[u] = hrow[idx * 16 + j];
        }

        unsigned mu = 0u;       // stale-by-1 lane-local max of exchanged bits

#pragma unroll
        for (int u = 0; u < 8; u++) {
            const bool act = (s0 + u) < cnt;     // per-lane FSEL
            float* buf = pbuf[u & 1][wid][grp];
            buf[j] = p;
            __syncwarp();
            const ulonglong2* bp = (const ulonglong2*)buf;
            const ulonglong2 v0 = bp[0];
            const ulonglong2 v1 = bp[1];
            const ulonglong2 v2 = bp[2];
            const ulonglong2 v3 = bp[3];

            u64 a0 = fma2(v0.y, EtrP[1], mul2(v0.x, EtrP[0]));
            u64 a1 = fma2(v1.y, EtrP[3], mul2(v1.x, EtrP[2]));
            u64 a2 = fma2(v2.y, EtrP[5], mul2(v2.x, EtrP[4]));
            u64 a3 = fma2(v3.y, EtrP[7], mul2(v3.x, EtrP[6]));
            float S = hadd2(add2(add2(a0, a1), add2(a2, a3)));
            float pn = S * eh[u];
            p = act ? pn : p;

            if (u == 7) {
                unsigned m0 = max((unsigned)v0.x, (unsigned)(v0.x >> 32));
                unsigned m1 = max((unsigned)v0.y, (unsigned)(v0.y >> 32));
                unsigned m2 = max((unsigned)v1.x, (unsigned)(v1.x >> 32));
                unsigned m3 = max((unsigned)v1.y, (unsigned)(v1.y >> 32));
                unsigned m4 = max((unsigned)v2.x, (unsigned)(v2.x >> 32));
                unsigned m5 = max((unsigned)v2.y, (unsigned)(v2.y >> 32));
                unsigned m6 = max((unsigned)v3.x, (unsigned)(v3.x >> 32));
                unsigned m7 = max((unsigned)v3.y, (unsigned)(v3.y >> 32));
                mu = max(max(max(m0, m1), max(m2, m3)),
                         max(max(m4, m5), max(m6, m7)));
            }
        }
        // exponent-only renorm: exact power-of-2 scaling
        int me = (int)(mu >> 23);
        me = (me < 1) ? 1 : me;
        float scale = __uint_as_float((unsigned)(254 - me) << 23);  // 2^(127-me)
        C += (float)(me - 127) * 0.6931471805599453f;
        p *= scale;
    }

    // ---- stitch: score = C_f + C_b + ln( sum_j w_m[j] * (Etr p_m)[j] ) ----
    {
        float* buf = pbuf[0][wid][grp];
        buf[j] = p;
        __syncwarp();
        const ulonglong2* bp = (const ulonglong2*)buf;
        const ulonglong2 v0 = bp[0];
        const ulonglong2 v1 = bp[1];
        const ulonglong2 v2 = bp[2];
        const ulonglong2 v3 = bp[3];
        u64 a0 = fma2(v0.y, EtrP[1], mul2(v0.x, EtrP[0]));
        u64 a1 = fma2(v1.y, EtrP[3], mul2(v1.x, EtrP[2]));
        u64 a2 = fma2(v2.y, EtrP[5], mul2(v2.x, EtrP[4]));
        u64 a3 = fma2(v3.y, EtrP[7], mul2(v3.x, EtrP[6]));
        float S = hadd2(add2(add2(a0, a1), add2(a2, a3)));  // fwd lanes: (Etr p_m)[j]

        float wsw = __shfl_xor_sync(0xFFFFFFFFu, p, 16);    // fwd lane j <- w_m[j]
        float Csw = __shfl_xor_sync(0xFFFFFFFFu, C, 16);    // fwd lane <- C_b

        float v = S * wsw;
#pragma unroll
        for (int s = 8; s; s >>= 1)
            v += __shfl_xor_sync(0xFFFFFFFFu, v, s, 16);

        if (lane == 0) {
            float fwd = C + Csw + __logf(v);
            g_row_out[row] = fwd - gold;
        }
    }

    // ---- last-block mean reduction ----
    __threadfence();
    __syncthreads();
    if (tid == 0) {
        int old = atomicAdd(&g_ctr, 1);
        s_last = (old == gridDim.x - 1);
    }
    __syncthreads();
    if (s_last) {
        float s = 0.f;
#pragma unroll
        for (int i = 0; i < BROWS / 128; i++)
            s += g_row_out[tid + i * 128];
#pragma unroll
        for (int sft = 16; sft; sft >>= 1)
            s += __shfl_xor_sync(0xFFFFFFFFu, s, sft);
        if ((tid & 31) == 0) s_red[tid >> 5] = s;
        __syncthreads();
        if (tid == 0) {
            float tot = s_red[0] + s_red[1] + s_red[2] + s_red[3];
            out[0] = tot * (1.0f / (float)BROWS);
            g_ctr = 0;   // reset for next graph replay
        }
    }
}

// ---------------------------------------------------------------------------
extern "C" void kernel_launch(void* const* d_in, const int* in_sizes, int n_in,
                              void* d_out, int out_size) {
    const float* h     = (const float*)d_in[0];
    const int*   y     = (const int*)d_in[1];
    const float* mask  = (const float*)d_in[2];
    const float* trans = (const float*)d_in[3];
    float* out = (float*)d_out;

    crf_fused_kernel<<<BROWS / 4, 128>>>(h, y, mask, trans, out);
}